// round 1
// baseline (speedup 1.0000x reference)
#include <cuda_runtime.h>

// MinimalPhysicsModel: 50-step recurrent physics sim + MLP(11->64->64->2, tanh)
// One thread per batch element. Weights in shared memory (broadcast reads).
// All GEMV layers use packed fma.rn.f32x2 (2 fp32 FMAs per instruction).

#define STEPS   50
#define HID     64
#define NFEAT   11
#define EPS_F   1e-6f
#define DT_F    (1.0f/30.0f)
#define TPB     128

typedef unsigned long long u64;

__device__ __forceinline__ u64 pk2(float x, float y) {
    u64 r; asm("mov.b64 %0,{%1,%2};" : "=l"(r) : "f"(x), "f"(y)); return r;
}
__device__ __forceinline__ void upk2(u64 v, float& x, float& y) {
    asm("mov.b64 {%0,%1},%2;" : "=f"(x), "=f"(y) : "l"(v));
}
__device__ __forceinline__ u64 ffma2(u64 a, u64 b, u64 c) {
    u64 d; asm("fma.rn.f32x2 %0,%1,%2,%3;" : "=l"(d) : "l"(a), "l"(b), "l"(c)); return d;
}

// tanh via exp2-based exp; |err| ~1e-6, far below 1e-3 tolerance.
__device__ __forceinline__ float tanh_fast(float x) {
    float ax = fabsf(x);
    float e  = __expf(-2.0f * ax);
    float r  = __fdividef(1.0f - e, 1.0f + e);
    return copysignf(r, x);
}

// shared layout (floats): all offsets 16B-aligned
#define OFF_W1  0        // 11*64 = 704
#define OFF_B1  704      // 64
#define OFF_W2  768      // 64*64 = 4096
#define OFF_B2  4864     // 64
#define OFF_W3  4928     // 64*2 = 128  (pairs: (W3[k][0],W3[k][1]))
#define OFF_B3  5056     // 2
#define SM_FLOATS 5060

__global__ void __launch_bounds__(TPB)
phys_kernel(const float* __restrict__ inp,
            const float* __restrict__ W1, const float* __restrict__ b1,
            const float* __restrict__ W2, const float* __restrict__ b2,
            const float* __restrict__ W3, const float* __restrict__ b3,
            const float* __restrict__ grav, const float* __restrict__ fricp,
            float* __restrict__ out, int nB)
{
    __shared__ __align__(16) float sm[SM_FLOATS];
    int tid = threadIdx.x;

    for (int i = tid; i < 704;  i += TPB) sm[OFF_W1 + i] = W1[i];
    for (int i = tid; i < 64;   i += TPB) sm[OFF_B1 + i] = b1[i];
    for (int i = tid; i < 4096; i += TPB) sm[OFF_W2 + i] = W2[i];
    for (int i = tid; i < 64;   i += TPB) sm[OFF_B2 + i] = b2[i];
    for (int i = tid; i < 128;  i += TPB) sm[OFF_W3 + i] = W3[i];
    if (tid == 0) { sm[OFF_B3] = b3[0]; sm[OFF_B3 + 1] = b3[1]; }
    __syncthreads();

    int b = blockIdx.x * TPB + tid;
    if (b >= nB) return;

    const float* s0 = inp + (size_t)b * STEPS * 8;
    float p1x = s0[0], p1y = s0[1], p2x = s0[2], p2y = s0[3];
    float v1x = s0[4], v1y = s0[5], v2x = s0[6], v2y = s0[7];

    float g    = grav[0] * 40.0f;      // pixel_gravity
    float fric = fabsf(fricp[0]);

    float* ob = out + (size_t)b * STEPS * 8;

    const u64* pW1 = (const u64*)(sm + OFF_W1);   // [11][32] pairs
    const u64* pB1 = (const u64*)(sm + OFF_B1);   // [32]
    const u64* pW2 = (const u64*)(sm + OFF_W2);   // [64][32] pairs
    const u64* pB2 = (const u64*)(sm + OFF_B2);   // [32]
    const u64* pW3 = (const u64*)(sm + OFF_W3);   // [64] pairs (out0,out1)

#pragma unroll 1
    for (int t = 0; t < STEPS; t++) {
        // emit pre-update state: out[b][t][0..7]
        float4 o0 = make_float4(p1x, p1y, p2x, p2y);
        float4 o1 = make_float4(v1x, v1y, v2x, v2y);
        *(float4*)(ob + t * 8)     = o0;
        *(float4*)(ob + t * 8 + 4) = o1;

        // ---- features ----
        float r1  = sqrtf(p1x * p1x + p1y * p1y);
        float th1 = atan2f(p1y, p1x);
        float vr1 = __fdividef(p1x * v1x + p1y * v1y, r1 + EPS_F);
        float vt1 = __fdividef(p1x * v1y - p1y * v1x, r1 * r1 + EPS_F);
        float L1  = r1 * vt1;

        float r2  = sqrtf(p2x * p2x + p2y * p2y);
        float th2 = atan2f(p2y, p2x);
        float vr2 = __fdividef(p2x * v2x + p2y * v2y, r2 + EPS_F);
        float vt2 = __fdividef(p2x * v2y - p2y * v2x, r2 * r2 + EPS_F);
        float L2  = r2 * vt2;

        float dx = p2x - p1x, dy = p2y - p1y;
        float r12 = sqrtf(dx * dx + dy * dy);

        float f[NFEAT] = { r1, th1, vr1, vt1, L1, r2, th2, vr2, vt2, L2, r12 };

        // ---- layer 1: 11 -> 64 (pre-activation pairs) ----
        u64 a1[32];
#pragma unroll
        for (int j = 0; j < 32; j++) a1[j] = pB1[j];
#pragma unroll
        for (int i = 0; i < NFEAT; i++) {
            u64 fi = pk2(f[i], f[i]);
            const u64* row = pW1 + i * 32;
#pragma unroll
            for (int j = 0; j < 32; j++) a1[j] = ffma2(fi, row[j], a1[j]);
        }

        // ---- layer 2: 64 -> 64, consuming tanh(a1) incrementally ----
        u64 a2[32];
#pragma unroll
        for (int j = 0; j < 32; j++) a2[j] = pB2[j];
#pragma unroll
        for (int k = 0; k < 32; k++) {
            float x0, x1; upk2(a1[k], x0, x1);
            float h0 = tanh_fast(x0);
            float h1 = tanh_fast(x1);
            u64 h0p = pk2(h0, h0);
            u64 h1p = pk2(h1, h1);
            const u64* row0 = pW2 + (2 * k) * 32;
            const u64* row1 = pW2 + (2 * k + 1) * 32;
#pragma unroll
            for (int j = 0; j < 32; j++) {
                a2[j] = ffma2(h0p, row0[j], a2[j]);
                a2[j] = ffma2(h1p, row1[j], a2[j]);
            }
        }

        // ---- layer 3: 64 -> 2, 4 partial accumulators for ILP ----
        u64 c0 = pk2(sm[OFF_B3], sm[OFF_B3 + 1]);
        u64 c1 = pk2(0.0f, 0.0f), c2 = pk2(0.0f, 0.0f), c3 = pk2(0.0f, 0.0f);
#pragma unroll
        for (int k = 0; k < 32; k += 2) {
            float x0, x1, y0, y1;
            upk2(a2[k],     x0, x1);
            upk2(a2[k + 1], y0, y1);
            float h0 = tanh_fast(x0), h1 = tanh_fast(x1);
            float h2 = tanh_fast(y0), h3 = tanh_fast(y1);
            c0 = ffma2(pk2(h0, h0), pW3[2 * k],     c0);
            c1 = ffma2(pk2(h1, h1), pW3[2 * k + 1], c1);
            c2 = ffma2(pk2(h2, h2), pW3[2 * k + 2], c2);
            c3 = ffma2(pk2(h3, h3), pW3[2 * k + 3], c3);
        }
        float ca, cb, cc, cd, ce, cf, cg2, ch;
        upk2(c0, ca, cb); upk2(c1, cc, cd); upk2(c2, ce, cf); upk2(c3, cg2, ch);
        float corrx = (ca + cc + ce + cg2) * 0.1f;
        float corry = (cb + cd + cf + ch)  * 0.1f;

        // ---- integrate ----
        float a1x = corrx - fric * v1x;
        float a1y = g + corry - fric * v1y;
        float a2x = corrx - fric * v2x;
        float a2y = g + corry - fric * v2y;

        v1x += a1x * DT_F;  v1y += a1y * DT_F;
        v2x += a2x * DT_F;  v2y += a2y * DT_F;
        p1x += v1x * DT_F;  p1y += v1y * DT_F;
        p2x += v2x * DT_F;  p2y += v2y * DT_F;

        // ---- bounce (hi_y = 580 for both balls) ----
        bool m;
        m = (p1x < 20.0f) || (p1x > 780.0f); v1x = m ? -0.8f * v1x : v1x;
        p1x = fminf(fmaxf(p1x, 20.0f), 780.0f);
        m = (p1y < 20.0f) || (p1y > 580.0f); v1y = m ? -0.8f * v1y : v1y;
        p1y = fminf(fmaxf(p1y, 20.0f), 580.0f);

        m = (p2x < 20.0f) || (p2x > 780.0f); v2x = m ? -0.8f * v2x : v2x;
        p2x = fminf(fmaxf(p2x, 20.0f), 780.0f);
        m = (p2y < 20.0f) || (p2y > 580.0f); v2y = m ? -0.8f * v2y : v2y;
        p2y = fminf(fmaxf(p2y, 20.0f), 580.0f);
    }
}

extern "C" void kernel_launch(void* const* d_in, const int* in_sizes, int n_in,
                              void* d_out, int out_size) {
    const float* inp  = (const float*)d_in[0];
    const float* W1   = (const float*)d_in[1];
    const float* b1   = (const float*)d_in[2];
    const float* W2   = (const float*)d_in[3];
    const float* b2   = (const float*)d_in[4];
    const float* W3   = (const float*)d_in[5];
    const float* b3   = (const float*)d_in[6];
    const float* grav = (const float*)d_in[7];
    const float* fric = (const float*)d_in[8];
    float* out = (float*)d_out;

    int nB = in_sizes[0] / (STEPS * 8);
    int grid = (nB + TPB - 1) / TPB;
    phys_kernel<<<grid, TPB>>>(inp, W1, b1, W2, b2, W3, b3, grav, fric, out, nB);
}

// round 2
// speedup vs baseline: 1.0243x; 1.0243x over previous
#include <cuda_runtime.h>

// MinimalPhysicsModel: 50-step recurrent physics sim + MLP(11->64->64->2, tanh)
// One thread per batch element. Weights in shared memory (broadcast LDS.128).
// GEMV layers use packed fma.rn.f32x2. Layer-2 computed in two j-half passes
// so peak live registers stay under 128 -> 4 blocks/SM (25% occupancy).

#define STEPS   50
#define HID     64
#define NFEAT   11
#define EPS_F   1e-6f
#define DT_F    (1.0f/30.0f)
#define TPB     128

typedef unsigned long long u64;

__device__ __forceinline__ u64 pk2(float x, float y) {
    u64 r; asm("mov.b64 %0,{%1,%2};" : "=l"(r) : "f"(x), "f"(y)); return r;
}
__device__ __forceinline__ void upk2(u64 v, float& x, float& y) {
    asm("mov.b64 {%0,%1},%2;" : "=f"(x), "=f"(y) : "l"(v));
}
__device__ __forceinline__ u64 ffma2(u64 a, u64 b, u64 c) {
    u64 d; asm("fma.rn.f32x2 %0,%1,%2,%3;" : "=l"(d) : "l"(a), "l"(b), "l"(c)); return d;
}

// tanh via exp; |err| ~1e-6, far below 1e-3 tolerance.
__device__ __forceinline__ float tanh_fast(float x) {
    float ax = fabsf(x);
    float e  = __expf(-2.0f * ax);
    float r  = __fdividef(1.0f - e, 1.0f + e);
    return copysignf(r, x);
}

// shared layout (floats): all offsets 16B-aligned
#define OFF_W1  0        // 11*64 = 704
#define OFF_B1  704      // 64
#define OFF_W2  768      // 64*64 = 4096
#define OFF_B2  4864     // 64
#define OFF_W3  4928     // 64*2 = 128  (pairs: (W3[k][0],W3[k][1]))
#define OFF_B3  5056     // 2
#define SM_FLOATS 5060

__global__ void __launch_bounds__(TPB, 4)
phys_kernel(const float* __restrict__ inp,
            const float* __restrict__ W1, const float* __restrict__ b1,
            const float* __restrict__ W2, const float* __restrict__ b2,
            const float* __restrict__ W3, const float* __restrict__ b3,
            const float* __restrict__ grav, const float* __restrict__ fricp,
            float* __restrict__ out, int nB)
{
    __shared__ __align__(16) float sm[SM_FLOATS];
    int tid = threadIdx.x;

    for (int i = tid; i < 704;  i += TPB) sm[OFF_W1 + i] = W1[i];
    for (int i = tid; i < 64;   i += TPB) sm[OFF_B1 + i] = b1[i];
    for (int i = tid; i < 4096; i += TPB) sm[OFF_W2 + i] = W2[i];
    for (int i = tid; i < 64;   i += TPB) sm[OFF_B2 + i] = b2[i];
    for (int i = tid; i < 128;  i += TPB) sm[OFF_W3 + i] = W3[i];
    if (tid == 0) { sm[OFF_B3] = b3[0]; sm[OFF_B3 + 1] = b3[1]; }
    __syncthreads();

    int b = blockIdx.x * TPB + tid;
    if (b >= nB) return;

    const float* s0 = inp + (size_t)b * STEPS * 8;
    float p1x = s0[0], p1y = s0[1], p2x = s0[2], p2y = s0[3];
    float v1x = s0[4], v1y = s0[5], v2x = s0[6], v2y = s0[7];

    float g    = grav[0] * 40.0f;      // pixel_gravity
    float fric = fabsf(fricp[0]);

    float* ob = out + (size_t)b * STEPS * 8;

    const ulonglong2* W1q = (const ulonglong2*)(sm + OFF_W1);  // [11][16] quads
    const u64*        pB1 = (const u64*)(sm + OFF_B1);         // [32]
    const ulonglong2* W2q = (const ulonglong2*)(sm + OFF_W2);  // [64][16] quads
    const u64*        pB2 = (const u64*)(sm + OFF_B2);         // [32]
    const u64*        pW3 = (const u64*)(sm + OFF_W3);         // [64] pairs

#pragma unroll 1
    for (int t = 0; t < STEPS; t++) {
        // emit pre-update state: out[b][t][0..7]
        *(float4*)(ob + t * 8)     = make_float4(p1x, p1y, p2x, p2y);
        *(float4*)(ob + t * 8 + 4) = make_float4(v1x, v1y, v2x, v2y);

        // ---- features ----
        float r1  = sqrtf(p1x * p1x + p1y * p1y);
        float th1 = atan2f(p1y, p1x);
        float vr1 = __fdividef(p1x * v1x + p1y * v1y, r1 + EPS_F);
        float vt1 = __fdividef(p1x * v1y - p1y * v1x, r1 * r1 + EPS_F);
        float L1  = r1 * vt1;

        float r2  = sqrtf(p2x * p2x + p2y * p2y);
        float th2 = atan2f(p2y, p2x);
        float vr2 = __fdividef(p2x * v2x + p2y * v2y, r2 + EPS_F);
        float vt2 = __fdividef(p2x * v2y - p2y * v2x, r2 * r2 + EPS_F);
        float L2  = r2 * vt2;

        float dx = p2x - p1x, dy = p2y - p1y;
        float r12 = sqrtf(dx * dx + dy * dy);

        float f[NFEAT] = { r1, th1, vr1, vt1, L1, r2, th2, vr2, vt2, L2, r12 };

        // ---- layer 1: 11 -> 64, then tanh into h[64] (a1 regs die) ----
        float h[HID];
        {
            u64 a1[32];
#pragma unroll
            for (int j = 0; j < 32; j++) a1[j] = pB1[j];
#pragma unroll
            for (int i = 0; i < NFEAT; i++) {
                u64 fi = pk2(f[i], f[i]);
#pragma unroll
                for (int q = 0; q < 16; q++) {
                    ulonglong2 w = W1q[i * 16 + q];
                    a1[2 * q]     = ffma2(fi, w.x, a1[2 * q]);
                    a1[2 * q + 1] = ffma2(fi, w.y, a1[2 * q + 1]);
                }
            }
#pragma unroll
            for (int j = 0; j < 32; j++) {
                float x0, x1; upk2(a1[j], x0, x1);
                h[2 * j]     = tanh_fast(x0);
                h[2 * j + 1] = tanh_fast(x1);
            }
        }

        // ---- layer 2 (two j-half passes) + layer 3 fused per pass ----
        u64 c0 = pk2(sm[OFF_B3], sm[OFF_B3 + 1]);
        u64 c1 = pk2(0.0f, 0.0f), c2 = pk2(0.0f, 0.0f), c3 = pk2(0.0f, 0.0f);

#pragma unroll
        for (int p = 0; p < 2; p++) {
            u64 a2[16];
#pragma unroll
            for (int j = 0; j < 16; j++) a2[j] = pB2[p * 16 + j];

#pragma unroll
            for (int k = 0; k < HID; k++) {
                u64 hk = pk2(h[k], h[k]);
#pragma unroll
                for (int q = 0; q < 8; q++) {
                    ulonglong2 w = W2q[k * 16 + p * 8 + q];
                    a2[2 * q]     = ffma2(hk, w.x, a2[2 * q]);
                    a2[2 * q + 1] = ffma2(hk, w.y, a2[2 * q + 1]);
                }
            }

            // layer 3 partial for this half (hidden idx n = p*32 + 2j, +1)
#pragma unroll
            for (int j = 0; j < 16; j += 2) {
                float x0, x1, y0, y1;
                upk2(a2[j],     x0, x1);
                upk2(a2[j + 1], y0, y1);
                float g0 = tanh_fast(x0), g1 = tanh_fast(x1);
                float g2 = tanh_fast(y0), g3 = tanh_fast(y1);
                int n = p * 32 + 2 * j;
                c0 = ffma2(pk2(g0, g0), pW3[n],     c0);
                c1 = ffma2(pk2(g1, g1), pW3[n + 1], c1);
                c2 = ffma2(pk2(g2, g2), pW3[n + 2], c2);
                c3 = ffma2(pk2(g3, g3), pW3[n + 3], c3);
            }
        }

        float ca, cb, cc, cd, ce, cf, cg2, ch;
        upk2(c0, ca, cb); upk2(c1, cc, cd); upk2(c2, ce, cf); upk2(c3, cg2, ch);
        float corrx = (ca + cc + ce + cg2) * 0.1f;
        float corry = (cb + cd + cf + ch)  * 0.1f;

        // ---- integrate ----
        float a1x = corrx - fric * v1x;
        float a1y = g + corry - fric * v1y;
        float a2x = corrx - fric * v2x;
        float a2y = g + corry - fric * v2y;

        v1x += a1x * DT_F;  v1y += a1y * DT_F;
        v2x += a2x * DT_F;  v2y += a2y * DT_F;
        p1x += v1x * DT_F;  p1y += v1y * DT_F;
        p2x += v2x * DT_F;  p2y += v2y * DT_F;

        // ---- bounce (hi_y = 580 for both balls) ----
        bool m;
        m = (p1x < 20.0f) || (p1x > 780.0f); v1x = m ? -0.8f * v1x : v1x;
        p1x = fminf(fmaxf(p1x, 20.0f), 780.0f);
        m = (p1y < 20.0f) || (p1y > 580.0f); v1y = m ? -0.8f * v1y : v1y;
        p1y = fminf(fmaxf(p1y, 20.0f), 580.0f);

        m = (p2x < 20.0f) || (p2x > 780.0f); v2x = m ? -0.8f * v2x : v2x;
        p2x = fminf(fmaxf(p2x, 20.0f), 780.0f);
        m = (p2y < 20.0f) || (p2y > 580.0f); v2y = m ? -0.8f * v2y : v2y;
        p2y = fminf(fmaxf(p2y, 20.0f), 580.0f);
    }
}

extern "C" void kernel_launch(void* const* d_in, const int* in_sizes, int n_in,
                              void* d_out, int out_size) {
    const float* inp  = (const float*)d_in[0];
    const float* W1   = (const float*)d_in[1];
    const float* b1   = (const float*)d_in[2];
    const float* W2   = (const float*)d_in[3];
    const float* b2   = (const float*)d_in[4];
    const float* W3   = (const float*)d_in[5];
    const float* b3   = (const float*)d_in[6];
    const float* grav = (const float*)d_in[7];
    const float* fric = (const float*)d_in[8];
    float* out = (float*)d_out;

    int nB = in_sizes[0] / (STEPS * 8);
    int grid = (nB + TPB - 1) / TPB;
    phys_kernel<<<grid, TPB>>>(inp, W1, b1, W2, b2, W3, b3, grav, fric, out, nB);
}

// round 3
// speedup vs baseline: 1.8819x; 1.8372x over previous
#include <cuda_runtime.h>

// MinimalPhysicsModel: 50-step recurrent sim + MLP(11->64->64->2, tanh).
// TWO threads per batch element (lane pair, j-dim split): each thread owns
// half of the hidden units. Partner activations exchanged via shfl_xor.
// Packed fma.rn.f32x2 throughout; weights broadcast from shared memory.

#define STEPS   50
#define HID     64
#define NFEAT   11
#define EPS_F   1e-6f
#define DT_F    (1.0f/30.0f)
#define TPB     128

typedef unsigned long long u64;

__device__ __forceinline__ u64 pk2(float x, float y) {
    u64 r; asm("mov.b64 %0,{%1,%2};" : "=l"(r) : "f"(x), "f"(y)); return r;
}
__device__ __forceinline__ void upk2(u64 v, float& x, float& y) {
    asm("mov.b64 {%0,%1},%2;" : "=f"(x), "=f"(y) : "l"(v));
}
__device__ __forceinline__ u64 ffma2(u64 a, u64 b, u64 c) {
    u64 d; asm("fma.rn.f32x2 %0,%1,%2,%3;" : "=l"(d) : "l"(a), "l"(b), "l"(c)); return d;
}

// tanh via exp; |err| ~1e-6, far below 1e-3 tolerance.
__device__ __forceinline__ float tanh_fast(float x) {
    float ax = fabsf(x);
    float e  = __expf(-2.0f * ax);
    float r  = __fdividef(1.0f - e, 1.0f + e);
    return copysignf(r, x);
}

// shared layout (floats): all offsets 16B-aligned
#define OFF_W1  0        // 11*64 = 704
#define OFF_B1  704      // 64
#define OFF_W2  768      // 64*64 = 4096
#define OFF_B2  4864     // 64
#define OFF_W3  4928     // 64*2 = 128  (pairs: (W3[k][0],W3[k][1]))
#define OFF_B3  5056     // 2
#define SM_FLOATS 5060

__global__ void __launch_bounds__(TPB, 5)
phys_kernel(const float* __restrict__ inp,
            const float* __restrict__ W1, const float* __restrict__ b1,
            const float* __restrict__ W2, const float* __restrict__ b2,
            const float* __restrict__ W3, const float* __restrict__ b3,
            const float* __restrict__ grav, const float* __restrict__ fricp,
            float* __restrict__ out, int nB)
{
    __shared__ __align__(16) float sm[SM_FLOATS];
    int tid = threadIdx.x;

    for (int i = tid; i < 704;  i += TPB) sm[OFF_W1 + i] = W1[i];
    for (int i = tid; i < 64;   i += TPB) sm[OFF_B1 + i] = b1[i];
    for (int i = tid; i < 4096; i += TPB) sm[OFF_W2 + i] = W2[i];
    for (int i = tid; i < 64;   i += TPB) sm[OFF_B2 + i] = b2[i];
    for (int i = tid; i < 128;  i += TPB) sm[OFF_W3 + i] = W3[i];
    if (tid == 0) { sm[OFF_B3] = b3[0]; sm[OFF_B3 + 1] = b3[1]; }
    __syncthreads();

    int gt   = blockIdx.x * TPB + tid;
    int e    = gt >> 1;          // element index (2 threads per element)
    int half = tid & 1;          // 0: hidden units 0..31, 1: 32..63
    if (e >= nB) return;

    const float* s0 = inp + (size_t)e * STEPS * 8;
    float p1x = s0[0], p1y = s0[1], p2x = s0[2], p2y = s0[3];
    float v1x = s0[4], v1y = s0[5], v2x = s0[6], v2y = s0[7];

    float g    = grav[0] * 40.0f;
    float fric = fabsf(fricp[0]);

    float* ob = out + (size_t)e * STEPS * 8 + half * 4;  // even->pos4, odd->vel4

    const ulonglong2* W1q = (const ulonglong2*)(sm + OFF_W1);  // [11][16] quads
    const u64*        pB1 = (const u64*)(sm + OFF_B1);         // [32]
    const ulonglong2* W2q = (const ulonglong2*)(sm + OFF_W2);  // [64][16] quads
    const u64*        pB2 = (const u64*)(sm + OFF_B2);         // [32]
    const u64*        pW3 = (const u64*)(sm + OFF_W3);         // [64]

    int hq = half * 8;       // quad offset of own output-half within a row
    int hp = half * 16;      // pair offset of own half in biases
    int rowOwn     = half * 32;        // row base for own h values
    int rowPartner = 32 - half * 32;   // row base for partner h values

#pragma unroll 1
    for (int t = 0; t < STEPS; t++) {
        // emit pre-update state (even lane: positions, odd lane: velocities)
        *(float4*)(ob + t * 8) = half ? make_float4(v1x, v1y, v2x, v2y)
                                      : make_float4(p1x, p1y, p2x, p2y);

        // ---- features (computed redundantly by both lanes) ----
        float r1  = sqrtf(p1x * p1x + p1y * p1y);
        float th1 = atan2f(p1y, p1x);
        float vr1 = __fdividef(p1x * v1x + p1y * v1y, r1 + EPS_F);
        float vt1 = __fdividef(p1x * v1y - p1y * v1x, r1 * r1 + EPS_F);
        float L1  = r1 * vt1;

        float r2  = sqrtf(p2x * p2x + p2y * p2y);
        float th2 = atan2f(p2y, p2x);
        float vr2 = __fdividef(p2x * v2x + p2y * v2y, r2 + EPS_F);
        float vt2 = __fdividef(p2x * v2y - p2y * v2x, r2 * r2 + EPS_F);
        float L2  = r2 * vt2;

        float dx = p2x - p1x, dy = p2y - p1y;
        float r12 = sqrtf(dx * dx + dy * dy);

        float f[NFEAT] = { r1, th1, vr1, vt1, L1, r2, th2, vr2, vt2, L2, r12 };

        // ---- layer 1: 11 -> own 32 outputs ----
        float h[32];
        {
            u64 a1[16];
#pragma unroll
            for (int j = 0; j < 16; j++) a1[j] = pB1[hp + j];
#pragma unroll
            for (int i = 0; i < NFEAT; i++) {
                u64 fi = pk2(f[i], f[i]);
                const ulonglong2* row = W1q + i * 16 + hq;
#pragma unroll
                for (int q = 0; q < 8; q++) {
                    ulonglong2 w = row[q];
                    a1[2 * q]     = ffma2(fi, w.x, a1[2 * q]);
                    a1[2 * q + 1] = ffma2(fi, w.y, a1[2 * q + 1]);
                }
            }
#pragma unroll
            for (int j = 0; j < 16; j++) {
                float x0, x1; upk2(a1[j], x0, x1);
                h[2 * j]     = tanh_fast(x0);
                h[2 * j + 1] = tanh_fast(x1);
            }
        }

        // ---- layer 2: own 32 outputs, summing over all 64 hidden inputs ----
        u64 a2[16];
#pragma unroll
        for (int j = 0; j < 16; j++) a2[j] = pB2[hp + j];

#pragma unroll 8
        for (int k = 0; k < 32; k++) {
            float hpart = __shfl_xor_sync(0xffffffffu, h[k], 1);
            u64 hk = pk2(h[k], h[k]);
            u64 hz = pk2(hpart, hpart);
            const ulonglong2* rA = W2q + (rowOwn + k) * 16 + hq;
            const ulonglong2* rB = W2q + (rowPartner + k) * 16 + hq;
#pragma unroll
            for (int q = 0; q < 8; q++) {
                ulonglong2 wA = rA[q];
                a2[2 * q]     = ffma2(hk, wA.x, a2[2 * q]);
                a2[2 * q + 1] = ffma2(hk, wA.y, a2[2 * q + 1]);
            }
#pragma unroll
            for (int q = 0; q < 8; q++) {
                ulonglong2 wB = rB[q];
                a2[2 * q]     = ffma2(hz, wB.x, a2[2 * q]);
                a2[2 * q + 1] = ffma2(hz, wB.y, a2[2 * q + 1]);
            }
        }

        // ---- layer 3: partial dot over own 32, butterfly-combined ----
        u64 c0 = half ? pk2(0.0f, 0.0f) : pk2(sm[OFF_B3], sm[OFF_B3 + 1]);
        u64 c1 = pk2(0.0f, 0.0f);
#pragma unroll
        for (int j = 0; j < 16; j++) {
            float x0, x1; upk2(a2[j], x0, x1);
            float g0 = tanh_fast(x0);
            float g1 = tanh_fast(x1);
            int kg = rowOwn + 2 * j;
            c0 = ffma2(pk2(g0, g0), pW3[kg],     c0);
            c1 = ffma2(pk2(g1, g1), pW3[kg + 1], c1);
        }
        float sx, sy, tx, ty;
        upk2(c0, sx, sy); upk2(c1, tx, ty);
        sx += tx; sy += ty;                       // own partial (even incl. b3)
        float px = __shfl_xor_sync(0xffffffffu, sx, 1);
        float py = __shfl_xor_sync(0xffffffffu, sy, 1);
        float corrx = (sx + px) * 0.1f;           // commutative: both lanes identical
        float corry = (sy + py) * 0.1f;

        // ---- integrate ----
        float a1x = corrx - fric * v1x;
        float a1y = g + corry - fric * v1y;
        float a2x = corrx - fric * v2x;
        float a2y = g + corry - fric * v2y;

        v1x += a1x * DT_F;  v1y += a1y * DT_F;
        v2x += a2x * DT_F;  v2y += a2y * DT_F;
        p1x += v1x * DT_F;  p1y += v1y * DT_F;
        p2x += v2x * DT_F;  p2y += v2y * DT_F;

        // ---- bounce (hi_y = 580 for both balls) ----
        bool m;
        m = (p1x < 20.0f) || (p1x > 780.0f); v1x = m ? -0.8f * v1x : v1x;
        p1x = fminf(fmaxf(p1x, 20.0f), 780.0f);
        m = (p1y < 20.0f) || (p1y > 580.0f); v1y = m ? -0.8f * v1y : v1y;
        p1y = fminf(fmaxf(p1y, 20.0f), 580.0f);

        m = (p2x < 20.0f) || (p2x > 780.0f); v2x = m ? -0.8f * v2x : v2x;
        p2x = fminf(fmaxf(p2x, 20.0f), 780.0f);
        m = (p2y < 20.0f) || (p2y > 580.0f); v2y = m ? -0.8f * v2y : v2y;
        p2y = fminf(fmaxf(p2y, 20.0f), 580.0f);
    }
}

extern "C" void kernel_launch(void* const* d_in, const int* in_sizes, int n_in,
                              void* d_out, int out_size) {
    const float* inp  = (const float*)d_in[0];
    const float* W1   = (const float*)d_in[1];
    const float* b1   = (const float*)d_in[2];
    const float* W2   = (const float*)d_in[3];
    const float* b2   = (const float*)d_in[4];
    const float* W3   = (const float*)d_in[5];
    const float* b3   = (const float*)d_in[6];
    const float* grav = (const float*)d_in[7];
    const float* fric = (const float*)d_in[8];
    float* out = (float*)d_out;

    int nB = in_sizes[0] / (STEPS * 8);
    int nThreads = nB * 2;
    int grid = (nThreads + TPB - 1) / TPB;
    phys_kernel<<<grid, TPB>>>(inp, W1, b1, W2, b2, W3, b3, grav, fric, out, nB);
}

// round 4
// speedup vs baseline: 2.6294x; 1.3972x over previous
#include <cuda_runtime.h>

// MinimalPhysicsModel: 50-step recurrent sim + MLP(11->64->64->2, tanh).
// 2 threads per element pair-slot (j-dim half split, shfl_xor exchange) AND
// 2 elements per thread (E=2): every weight load from shared memory feeds
// 4 packed FFMA2 (2 accum pairs x 2 elements), halving crossbar traffic
// per element vs R3. Packed fma.rn.f32x2 throughout.

#define STEPS   50
#define HID     64
#define NFEAT   11
#define EPS_F   1e-6f
#define DT_F    (1.0f/30.0f)
#define TPB     128

typedef unsigned long long u64;

__device__ __forceinline__ u64 pk2(float x, float y) {
    u64 r; asm("mov.b64 %0,{%1,%2};" : "=l"(r) : "f"(x), "f"(y)); return r;
}
__device__ __forceinline__ void upk2(u64 v, float& x, float& y) {
    asm("mov.b64 {%0,%1},%2;" : "=f"(x), "=f"(y) : "l"(v));
}
__device__ __forceinline__ u64 ffma2(u64 a, u64 b, u64 c) {
    u64 d; asm("fma.rn.f32x2 %0,%1,%2,%3;" : "=l"(d) : "l"(a), "l"(b), "l"(c)); return d;
}

// tanh via exp; |err| ~1e-6, far below 1e-3 tolerance.
__device__ __forceinline__ float tanh_fast(float x) {
    float ax = fabsf(x);
    float e  = __expf(-2.0f * ax);
    float r  = __fdividef(1.0f - e, 1.0f + e);
    return copysignf(r, x);
}

// shared layout (floats): all offsets 16B-aligned
#define OFF_W1  0        // 11*64 = 704
#define OFF_B1  704      // 64
#define OFF_W2  768      // 64*64 = 4096
#define OFF_B2  4864     // 64
#define OFF_W3  4928     // 64*2 = 128  (pairs: (W3[k][0],W3[k][1]))
#define OFF_B3  5056     // 2
#define SM_FLOATS 5060

struct State {
    float p1x, p1y, p2x, p2y, v1x, v1y, v2x, v2y;
};

__device__ __forceinline__ void features(const State& s, float* f) {
    float r1  = sqrtf(s.p1x * s.p1x + s.p1y * s.p1y);
    float th1 = atan2f(s.p1y, s.p1x);
    float vr1 = __fdividef(s.p1x * s.v1x + s.p1y * s.v1y, r1 + EPS_F);
    float vt1 = __fdividef(s.p1x * s.v1y - s.p1y * s.v1x, r1 * r1 + EPS_F);
    float L1  = r1 * vt1;

    float r2  = sqrtf(s.p2x * s.p2x + s.p2y * s.p2y);
    float th2 = atan2f(s.p2y, s.p2x);
    float vr2 = __fdividef(s.p2x * s.v2x + s.p2y * s.v2y, r2 + EPS_F);
    float vt2 = __fdividef(s.p2x * s.v2y - s.p2y * s.v2x, r2 * r2 + EPS_F);
    float L2  = r2 * vt2;

    float dx = s.p2x - s.p1x, dy = s.p2y - s.p1y;
    float r12 = sqrtf(dx * dx + dy * dy);

    f[0] = r1;  f[1] = th1; f[2] = vr1; f[3] = vt1; f[4] = L1;
    f[5] = r2;  f[6] = th2; f[7] = vr2; f[8] = vt2; f[9] = L2;
    f[10] = r12;
}

__device__ __forceinline__ void integrate(State& s, float corrx, float corry,
                                          float g, float fric) {
    float a1x = corrx - fric * s.v1x;
    float a1y = g + corry - fric * s.v1y;
    float a2x = corrx - fric * s.v2x;
    float a2y = g + corry - fric * s.v2y;

    s.v1x += a1x * DT_F;  s.v1y += a1y * DT_F;
    s.v2x += a2x * DT_F;  s.v2y += a2y * DT_F;
    s.p1x += s.v1x * DT_F;  s.p1y += s.v1y * DT_F;
    s.p2x += s.v2x * DT_F;  s.p2y += s.v2y * DT_F;

    bool m;
    m = (s.p1x < 20.0f) || (s.p1x > 780.0f); s.v1x = m ? -0.8f * s.v1x : s.v1x;
    s.p1x = fminf(fmaxf(s.p1x, 20.0f), 780.0f);
    m = (s.p1y < 20.0f) || (s.p1y > 580.0f); s.v1y = m ? -0.8f * s.v1y : s.v1y;
    s.p1y = fminf(fmaxf(s.p1y, 20.0f), 580.0f);

    m = (s.p2x < 20.0f) || (s.p2x > 780.0f); s.v2x = m ? -0.8f * s.v2x : s.v2x;
    s.p2x = fminf(fmaxf(s.p2x, 20.0f), 780.0f);
    m = (s.p2y < 20.0f) || (s.p2y > 580.0f); s.v2y = m ? -0.8f * s.v2y : s.v2y;
    s.p2y = fminf(fmaxf(s.p2y, 20.0f), 580.0f);
}

__global__ void __launch_bounds__(TPB, 2)
phys_kernel(const float* __restrict__ inp,
            const float* __restrict__ W1, const float* __restrict__ b1,
            const float* __restrict__ W2, const float* __restrict__ b2,
            const float* __restrict__ W3, const float* __restrict__ b3,
            const float* __restrict__ grav, const float* __restrict__ fricp,
            float* __restrict__ out, int nB)
{
    __shared__ __align__(16) float sm[SM_FLOATS];
    int tid = threadIdx.x;

    for (int i = tid; i < 704;  i += TPB) sm[OFF_W1 + i] = W1[i];
    for (int i = tid; i < 64;   i += TPB) sm[OFF_B1 + i] = b1[i];
    for (int i = tid; i < 4096; i += TPB) sm[OFF_W2 + i] = W2[i];
    for (int i = tid; i < 64;   i += TPB) sm[OFF_B2 + i] = b2[i];
    for (int i = tid; i < 128;  i += TPB) sm[OFF_W3 + i] = W3[i];
    if (tid == 0) { sm[OFF_B3] = b3[0]; sm[OFF_B3 + 1] = b3[1]; }
    __syncthreads();

    int gt   = blockIdx.x * TPB + tid;
    int pair = gt >> 1;              // pair-slot index
    int half = tid & 1;              // 0: hidden 0..31, 1: hidden 32..63
    int e0   = pair * 2;             // first element of this thread
    if (e0 >= nB) return;
    int e1   = (e0 + 1 < nB) ? e0 + 1 : e0;   // second (dup-safe on odd tail)

    State S0, S1;
    {
        const float* s0 = inp + (size_t)e0 * STEPS * 8;
        S0.p1x = s0[0]; S0.p1y = s0[1]; S0.p2x = s0[2]; S0.p2y = s0[3];
        S0.v1x = s0[4]; S0.v1y = s0[5]; S0.v2x = s0[6]; S0.v2y = s0[7];
        const float* s1 = inp + (size_t)e1 * STEPS * 8;
        S1.p1x = s1[0]; S1.p1y = s1[1]; S1.p2x = s1[2]; S1.p2y = s1[3];
        S1.v1x = s1[4]; S1.v1y = s1[5]; S1.v2x = s1[6]; S1.v2y = s1[7];
    }

    float g    = grav[0] * 40.0f;
    float fric = fabsf(fricp[0]);

    float* ob0 = out + (size_t)e0 * STEPS * 8 + half * 4;
    float* ob1 = out + (size_t)e1 * STEPS * 8 + half * 4;

    const ulonglong2* W1q = (const ulonglong2*)(sm + OFF_W1);  // [11][16] quads
    const u64*        pB1 = (const u64*)(sm + OFF_B1);         // [32]
    const ulonglong2* W2q = (const ulonglong2*)(sm + OFF_W2);  // [64][16] quads
    const u64*        pB2 = (const u64*)(sm + OFF_B2);         // [32]
    const u64*        pW3 = (const u64*)(sm + OFF_W3);         // [64]

    int hq = half * 8;               // quad offset of own output-half in a row
    int hp = half * 16;              // pair offset of own half in biases
    int rowOwn     = half * 32;
    int rowPartner = 32 - half * 32;

#pragma unroll 1
    for (int t = 0; t < STEPS; t++) {
        // emit pre-update state (even lane: positions, odd lane: velocities)
        *(float4*)(ob0 + t * 8) = half ? make_float4(S0.v1x, S0.v1y, S0.v2x, S0.v2y)
                                       : make_float4(S0.p1x, S0.p1y, S0.p2x, S0.p2y);
        *(float4*)(ob1 + t * 8) = half ? make_float4(S1.v1x, S1.v1y, S1.v2x, S1.v2y)
                                       : make_float4(S1.p1x, S1.p1y, S1.p2x, S1.p2y);

        float f0[NFEAT], f1[NFEAT];
        features(S0, f0);
        features(S1, f1);

        // ---- layer 1: 11 -> own 32 outputs, both elements share loads ----
        float h0[32], h1[32];
        {
            u64 a0[16], a1v[16];
#pragma unroll
            for (int j = 0; j < 16; j++) { a0[j] = pB1[hp + j]; a1v[j] = a0[j]; }
#pragma unroll
            for (int i = 0; i < NFEAT; i++) {
                u64 fe0 = pk2(f0[i], f0[i]);
                u64 fe1 = pk2(f1[i], f1[i]);
                const ulonglong2* row = W1q + i * 16 + hq;
#pragma unroll
                for (int q = 0; q < 8; q++) {
                    ulonglong2 w = row[q];
                    a0[2 * q]      = ffma2(fe0, w.x, a0[2 * q]);
                    a0[2 * q + 1]  = ffma2(fe0, w.y, a0[2 * q + 1]);
                    a1v[2 * q]     = ffma2(fe1, w.x, a1v[2 * q]);
                    a1v[2 * q + 1] = ffma2(fe1, w.y, a1v[2 * q + 1]);
                }
            }
#pragma unroll
            for (int j = 0; j < 16; j++) {
                float x0, x1;
                upk2(a0[j], x0, x1);
                h0[2 * j] = tanh_fast(x0); h0[2 * j + 1] = tanh_fast(x1);
                upk2(a1v[j], x0, x1);
                h1[2 * j] = tanh_fast(x0); h1[2 * j + 1] = tanh_fast(x1);
            }
        }

        // ---- layer 2: own 32 outputs over all 64 hidden, shared loads ----
        u64 a20[16], a21[16];
#pragma unroll
        for (int j = 0; j < 16; j++) { a20[j] = pB2[hp + j]; a21[j] = a20[j]; }

#pragma unroll 4
        for (int k = 0; k < 32; k++) {
            float hp0 = __shfl_xor_sync(0xffffffffu, h0[k], 1);
            float hp1 = __shfl_xor_sync(0xffffffffu, h1[k], 1);
            u64 k00 = pk2(h0[k], h0[k]);
            u64 k10 = pk2(h1[k], h1[k]);
            u64 k01 = pk2(hp0, hp0);
            u64 k11 = pk2(hp1, hp1);
            const ulonglong2* rA = W2q + (rowOwn + k) * 16 + hq;
            const ulonglong2* rB = W2q + (rowPartner + k) * 16 + hq;
#pragma unroll
            for (int q = 0; q < 8; q++) {
                ulonglong2 w = rA[q];
                a20[2 * q]     = ffma2(k00, w.x, a20[2 * q]);
                a20[2 * q + 1] = ffma2(k00, w.y, a20[2 * q + 1]);
                a21[2 * q]     = ffma2(k10, w.x, a21[2 * q]);
                a21[2 * q + 1] = ffma2(k10, w.y, a21[2 * q + 1]);
            }
#pragma unroll
            for (int q = 0; q < 8; q++) {
                ulonglong2 w = rB[q];
                a20[2 * q]     = ffma2(k01, w.x, a20[2 * q]);
                a20[2 * q + 1] = ffma2(k01, w.y, a20[2 * q + 1]);
                a21[2 * q]     = ffma2(k11, w.x, a21[2 * q]);
                a21[2 * q + 1] = ffma2(k11, w.y, a21[2 * q + 1]);
            }
        }

        // ---- layer 3: partial dot over own 32, butterfly-combined ----
        u64 c00 = half ? pk2(0.0f, 0.0f) : pk2(sm[OFF_B3], sm[OFF_B3 + 1]);
        u64 c01 = pk2(0.0f, 0.0f);
        u64 c10 = c00, c11 = pk2(0.0f, 0.0f);
#pragma unroll
        for (int j = 0; j < 16; j++) {
            u64 w0 = pW3[rowOwn + 2 * j];
            u64 w1 = pW3[rowOwn + 2 * j + 1];
            float x0, x1;
            upk2(a20[j], x0, x1);
            float g0 = tanh_fast(x0), g1 = tanh_fast(x1);
            c00 = ffma2(pk2(g0, g0), w0, c00);
            c01 = ffma2(pk2(g1, g1), w1, c01);
            upk2(a21[j], x0, x1);
            float g2 = tanh_fast(x0), g3 = tanh_fast(x1);
            c10 = ffma2(pk2(g2, g2), w0, c10);
            c11 = ffma2(pk2(g3, g3), w1, c11);
        }
        float sx0, sy0, tx0, ty0, sx1, sy1, tx1, ty1;
        upk2(c00, sx0, sy0); upk2(c01, tx0, ty0);
        upk2(c10, sx1, sy1); upk2(c11, tx1, ty1);
        sx0 += tx0; sy0 += ty0;
        sx1 += tx1; sy1 += ty1;
        float px0 = __shfl_xor_sync(0xffffffffu, sx0, 1);
        float py0 = __shfl_xor_sync(0xffffffffu, sy0, 1);
        float px1 = __shfl_xor_sync(0xffffffffu, sx1, 1);
        float py1 = __shfl_xor_sync(0xffffffffu, sy1, 1);
        float cx0 = (sx0 + px0) * 0.1f, cy0 = (sy0 + py0) * 0.1f;
        float cx1 = (sx1 + px1) * 0.1f, cy1 = (sy1 + py1) * 0.1f;

        integrate(S0, cx0, cy0, g, fric);
        integrate(S1, cx1, cy1, g, fric);
    }
}

extern "C" void kernel_launch(void* const* d_in, const int* in_sizes, int n_in,
                              void* d_out, int out_size) {
    const float* inp  = (const float*)d_in[0];
    const float* W1   = (const float*)d_in[1];
    const float* b1   = (const float*)d_in[2];
    const float* W2   = (const float*)d_in[3];
    const float* b2   = (const float*)d_in[4];
    const float* W3   = (const float*)d_in[5];
    const float* b3   = (const float*)d_in[6];
    const float* grav = (const float*)d_in[7];
    const float* fric = (const float*)d_in[8];
    float* out = (float*)d_out;

    int nB = in_sizes[0] / (STEPS * 8);
    int nPairs = (nB + 1) / 2;          // element-pairs, 2 threads each
    int nThreads = nPairs * 2;
    int grid = (nThreads + TPB - 1) / TPB;
    phys_kernel<<<grid, TPB>>>(inp, W1, b1, W2, b2, W3, b3, grav, fric, out, nB);
}

// round 5
// speedup vs baseline: 2.6753x; 1.0175x over previous
#include <cuda_runtime.h>

// MinimalPhysicsModel: 50-step recurrent sim + MLP(11->64->64->2, tanh).
// 2 threads per element (j-dim half split, shfl_xor exchange) AND
// 2 elements per thread (E=2): every 16B weight load feeds 4 packed FFMA2.
// R5: 3 blocks/SM (regs capped 170) to raise issue coverage of LDS/SHFL latency.

#define STEPS   50
#define HID     64
#define NFEAT   11
#define EPS_F   1e-6f
#define DT_F    (1.0f/30.0f)
#define TPB     128

typedef unsigned long long u64;

__device__ __forceinline__ u64 pk2(float x, float y) {
    u64 r; asm("mov.b64 %0,{%1,%2};" : "=l"(r) : "f"(x), "f"(y)); return r;
}
__device__ __forceinline__ void upk2(u64 v, float& x, float& y) {
    asm("mov.b64 {%0,%1},%2;" : "=f"(x), "=f"(y) : "l"(v));
}
__device__ __forceinline__ u64 ffma2(u64 a, u64 b, u64 c) {
    u64 d; asm("fma.rn.f32x2 %0,%1,%2,%3;" : "=l"(d) : "l"(a), "l"(b), "l"(c)); return d;
}

// tanh = copysign(1 - 2e/(1+e), x), e = exp(-2|x|);  |err| ~1e-6.
__device__ __forceinline__ float tanh_fast(float x) {
    float ax = fabsf(x);
    float e;
    asm("ex2.approx.f32 %0, %1;" : "=f"(e) : "f"(ax * -2.885390082f)); // -2*log2(e)
    float rc;
    asm("rcp.approx.f32 %0, %1;" : "=f"(rc) : "f"(1.0f + e));
    float r = fmaf(-2.0f * e, rc, 1.0f);
    return copysignf(r, x);
}

// shared layout (floats): all offsets 16B-aligned
#define OFF_W1  0        // 11*64 = 704
#define OFF_B1  704      // 64
#define OFF_W2  768      // 64*64 = 4096
#define OFF_B2  4864     // 64
#define OFF_W3  4928     // 64*2 = 128
#define OFF_B3  5056     // 2
#define SM_FLOATS 5060

struct State {
    float p1x, p1y, p2x, p2y, v1x, v1y, v2x, v2y;
};

__device__ __forceinline__ void features(const State& s, float* f) {
    float r1  = sqrtf(s.p1x * s.p1x + s.p1y * s.p1y);
    float th1 = atan2f(s.p1y, s.p1x);
    float vr1 = __fdividef(s.p1x * s.v1x + s.p1y * s.v1y, r1 + EPS_F);
    float vt1 = __fdividef(s.p1x * s.v1y - s.p1y * s.v1x, r1 * r1 + EPS_F);
    float L1  = r1 * vt1;

    float r2  = sqrtf(s.p2x * s.p2x + s.p2y * s.p2y);
    float th2 = atan2f(s.p2y, s.p2x);
    float vr2 = __fdividef(s.p2x * s.v2x + s.p2y * s.v2y, r2 + EPS_F);
    float vt2 = __fdividef(s.p2x * s.v2y - s.p2y * s.v2x, r2 * r2 + EPS_F);
    float L2  = r2 * vt2;

    float dx = s.p2x - s.p1x, dy = s.p2y - s.p1y;
    float r12 = sqrtf(dx * dx + dy * dy);

    f[0] = r1;  f[1] = th1; f[2] = vr1; f[3] = vt1; f[4] = L1;
    f[5] = r2;  f[6] = th2; f[7] = vr2; f[8] = vt2; f[9] = L2;
    f[10] = r12;
}

__device__ __forceinline__ void integrate(State& s, float corrx, float corry,
                                          float g, float fric) {
    float a1x = corrx - fric * s.v1x;
    float a1y = g + corry - fric * s.v1y;
    float a2x = corrx - fric * s.v2x;
    float a2y = g + corry - fric * s.v2y;

    s.v1x += a1x * DT_F;  s.v1y += a1y * DT_F;
    s.v2x += a2x * DT_F;  s.v2y += a2y * DT_F;
    s.p1x += s.v1x * DT_F;  s.p1y += s.v1y * DT_F;
    s.p2x += s.v2x * DT_F;  s.p2y += s.v2y * DT_F;

    bool m;
    m = (s.p1x < 20.0f) || (s.p1x > 780.0f); s.v1x = m ? -0.8f * s.v1x : s.v1x;
    s.p1x = fminf(fmaxf(s.p1x, 20.0f), 780.0f);
    m = (s.p1y < 20.0f) || (s.p1y > 580.0f); s.v1y = m ? -0.8f * s.v1y : s.v1y;
    s.p1y = fminf(fmaxf(s.p1y, 20.0f), 580.0f);

    m = (s.p2x < 20.0f) || (s.p2x > 780.0f); s.v2x = m ? -0.8f * s.v2x : s.v2x;
    s.p2x = fminf(fmaxf(s.p2x, 20.0f), 780.0f);
    m = (s.p2y < 20.0f) || (s.p2y > 580.0f); s.v2y = m ? -0.8f * s.v2y : s.v2y;
    s.p2y = fminf(fmaxf(s.p2y, 20.0f), 580.0f);
}

__global__ void __launch_bounds__(TPB, 3)
phys_kernel(const float* __restrict__ inp,
            const float* __restrict__ W1, const float* __restrict__ b1,
            const float* __restrict__ W2, const float* __restrict__ b2,
            const float* __restrict__ W3, const float* __restrict__ b3,
            const float* __restrict__ grav, const float* __restrict__ fricp,
            float* __restrict__ out, int nB)
{
    __shared__ __align__(16) float sm[SM_FLOATS];
    int tid = threadIdx.x;

    for (int i = tid; i < 704;  i += TPB) sm[OFF_W1 + i] = W1[i];
    for (int i = tid; i < 64;   i += TPB) sm[OFF_B1 + i] = b1[i];
    for (int i = tid; i < 4096; i += TPB) sm[OFF_W2 + i] = W2[i];
    for (int i = tid; i < 64;   i += TPB) sm[OFF_B2 + i] = b2[i];
    for (int i = tid; i < 128;  i += TPB) sm[OFF_W3 + i] = W3[i];
    if (tid == 0) { sm[OFF_B3] = b3[0]; sm[OFF_B3 + 1] = b3[1]; }
    __syncthreads();

    int gt   = blockIdx.x * TPB + tid;
    int pair = gt >> 1;              // pair-slot index
    int half = tid & 1;              // 0: hidden 0..31, 1: hidden 32..63
    int e0   = pair * 2;
    if (e0 >= nB) return;
    int e1   = (e0 + 1 < nB) ? e0 + 1 : e0;

    State S0, S1;
    {
        const float* s0 = inp + (size_t)e0 * STEPS * 8;
        S0.p1x = s0[0]; S0.p1y = s0[1]; S0.p2x = s0[2]; S0.p2y = s0[3];
        S0.v1x = s0[4]; S0.v1y = s0[5]; S0.v2x = s0[6]; S0.v2y = s0[7];
        const float* s1 = inp + (size_t)e1 * STEPS * 8;
        S1.p1x = s1[0]; S1.p1y = s1[1]; S1.p2x = s1[2]; S1.p2y = s1[3];
        S1.v1x = s1[4]; S1.v1y = s1[5]; S1.v2x = s1[6]; S1.v2y = s1[7];
    }

    float g    = grav[0] * 40.0f;
    float fric = fabsf(fricp[0]);

    float* ob0 = out + (size_t)e0 * STEPS * 8 + half * 4;
    float* ob1 = out + (size_t)e1 * STEPS * 8 + half * 4;

    const ulonglong2* W1q = (const ulonglong2*)(sm + OFF_W1);
    const u64*        pB1 = (const u64*)(sm + OFF_B1);
    const ulonglong2* W2q = (const ulonglong2*)(sm + OFF_W2);
    const u64*        pB2 = (const u64*)(sm + OFF_B2);
    const u64*        pW3 = (const u64*)(sm + OFF_W3);

    int hq = half * 8;
    int hp = half * 16;
    int rowOwn     = half * 32;
    int rowPartner = 32 - half * 32;

#pragma unroll 1
    for (int t = 0; t < STEPS; t++) {
        *(float4*)(ob0 + t * 8) = half ? make_float4(S0.v1x, S0.v1y, S0.v2x, S0.v2y)
                                       : make_float4(S0.p1x, S0.p1y, S0.p2x, S0.p2y);
        *(float4*)(ob1 + t * 8) = half ? make_float4(S1.v1x, S1.v1y, S1.v2x, S1.v2y)
                                       : make_float4(S1.p1x, S1.p1y, S1.p2x, S1.p2y);

        float f0[NFEAT], f1[NFEAT];
        features(S0, f0);
        features(S1, f1);

        // ---- layer 1: 11 -> own 32 outputs, both elements share loads ----
        float h0[32], h1[32];
        {
            u64 a0[16], a1v[16];
#pragma unroll
            for (int j = 0; j < 16; j++) { a0[j] = pB1[hp + j]; a1v[j] = a0[j]; }
#pragma unroll
            for (int i = 0; i < NFEAT; i++) {
                u64 fe0 = pk2(f0[i], f0[i]);
                u64 fe1 = pk2(f1[i], f1[i]);
                const ulonglong2* row = W1q + i * 16 + hq;
#pragma unroll
                for (int q = 0; q < 8; q++) {
                    ulonglong2 w = row[q];
                    a0[2 * q]      = ffma2(fe0, w.x, a0[2 * q]);
                    a0[2 * q + 1]  = ffma2(fe0, w.y, a0[2 * q + 1]);
                    a1v[2 * q]     = ffma2(fe1, w.x, a1v[2 * q]);
                    a1v[2 * q + 1] = ffma2(fe1, w.y, a1v[2 * q + 1]);
                }
            }
#pragma unroll
            for (int j = 0; j < 16; j++) {
                float x0, x1;
                upk2(a0[j], x0, x1);
                h0[2 * j] = tanh_fast(x0); h0[2 * j + 1] = tanh_fast(x1);
                upk2(a1v[j], x0, x1);
                h1[2 * j] = tanh_fast(x0); h1[2 * j + 1] = tanh_fast(x1);
            }
        }

        // ---- layer 2: own 32 outputs over all 64 hidden, shared loads ----
        u64 a20[16], a21[16];
#pragma unroll
        for (int j = 0; j < 16; j++) { a20[j] = pB2[hp + j]; a21[j] = a20[j]; }

#pragma unroll 4
        for (int k = 0; k < 32; k++) {
            float hp0 = __shfl_xor_sync(0xffffffffu, h0[k], 1);
            float hp1 = __shfl_xor_sync(0xffffffffu, h1[k], 1);
            u64 k00 = pk2(h0[k], h0[k]);
            u64 k10 = pk2(h1[k], h1[k]);
            u64 k01 = pk2(hp0, hp0);
            u64 k11 = pk2(hp1, hp1);
            const ulonglong2* rA = W2q + (rowOwn + k) * 16 + hq;
            const ulonglong2* rB = W2q + (rowPartner + k) * 16 + hq;
#pragma unroll
            for (int q = 0; q < 8; q++) {
                ulonglong2 w = rA[q];
                a20[2 * q]     = ffma2(k00, w.x, a20[2 * q]);
                a20[2 * q + 1] = ffma2(k00, w.y, a20[2 * q + 1]);
                a21[2 * q]     = ffma2(k10, w.x, a21[2 * q]);
                a21[2 * q + 1] = ffma2(k10, w.y, a21[2 * q + 1]);
            }
#pragma unroll
            for (int q = 0; q < 8; q++) {
                ulonglong2 w = rB[q];
                a20[2 * q]     = ffma2(k01, w.x, a20[2 * q]);
                a20[2 * q + 1] = ffma2(k01, w.y, a20[2 * q + 1]);
                a21[2 * q]     = ffma2(k11, w.x, a21[2 * q]);
                a21[2 * q + 1] = ffma2(k11, w.y, a21[2 * q + 1]);
            }
        }

        // ---- layer 3: partial dot over own 32, butterfly-combined ----
        u64 c00 = half ? pk2(0.0f, 0.0f) : pk2(sm[OFF_B3], sm[OFF_B3 + 1]);
        u64 c01 = pk2(0.0f, 0.0f);
        u64 c10 = c00, c11 = pk2(0.0f, 0.0f);
#pragma unroll
        for (int j = 0; j < 16; j++) {
            u64 w0 = pW3[rowOwn + 2 * j];
            u64 w1 = pW3[rowOwn + 2 * j + 1];
            float x0, x1;
            upk2(a20[j], x0, x1);
            float g0 = tanh_fast(x0), g1 = tanh_fast(x1);
            c00 = ffma2(pk2(g0, g0), w0, c00);
            c01 = ffma2(pk2(g1, g1), w1, c01);
            upk2(a21[j], x0, x1);
            float g2 = tanh_fast(x0), g3 = tanh_fast(x1);
            c10 = ffma2(pk2(g2, g2), w0, c10);
            c11 = ffma2(pk2(g3, g3), w1, c11);
        }
        float sx0, sy0, tx0, ty0, sx1, sy1, tx1, ty1;
        upk2(c00, sx0, sy0); upk2(c01, tx0, ty0);
        upk2(c10, sx1, sy1); upk2(c11, tx1, ty1);
        sx0 += tx0; sy0 += ty0;
        sx1 += tx1; sy1 += ty1;
        float px0 = __shfl_xor_sync(0xffffffffu, sx0, 1);
        float py0 = __shfl_xor_sync(0xffffffffu, sy0, 1);
        float px1 = __shfl_xor_sync(0xffffffffu, sx1, 1);
        float py1 = __shfl_xor_sync(0xffffffffu, sy1, 1);
        float cx0 = (sx0 + px0) * 0.1f, cy0 = (sy0 + py0) * 0.1f;
        float cx1 = (sx1 + px1) * 0.1f, cy1 = (sy1 + py1) * 0.1f;

        integrate(S0, cx0, cy0, g, fric);
        integrate(S1, cx1, cy1, g, fric);
    }
}

extern "C" void kernel_launch(void* const* d_in, const int* in_sizes, int n_in,
                              void* d_out, int out_size) {
    const float* inp  = (const float*)d_in[0];
    const float* W1   = (const float*)d_in[1];
    const float* b1   = (const float*)d_in[2];
    const float* W2   = (const float*)d_in[3];
    const float* b2   = (const float*)d_in[4];
    const float* W3   = (const float*)d_in[5];
    const float* b3   = (const float*)d_in[6];
    const float* grav = (const float*)d_in[7];
    const float* fric = (const float*)d_in[8];
    float* out = (float*)d_out;

    int nB = in_sizes[0] / (STEPS * 8);
    int nPairs = (nB + 1) / 2;
    int nThreads = nPairs * 2;
    int grid = (nThreads + TPB - 1) / TPB;
    phys_kernel<<<grid, TPB>>>(inp, W1, b1, W2, b2, W3, b3, grav, fric, out, nB);
}

// round 6
// speedup vs baseline: 3.0068x; 1.1239x over previous
#include <cuda_runtime.h>

// MinimalPhysicsModel: 50-step recurrent sim + MLP(11->64->64->2, tanh).
// S=4 lanes per element-slot (each lane owns 16 of 64 hidden units),
// E=4 elements per slot (one element's state per lane). Every 16B weight
// load from shared memory feeds 8 packed FFMA2 (2 pairs x 4 elements).
// Hidden activations staged through padded SMEM (stride 272B).

#define STEPS   50
#define HID     64
#define NFEAT   11
#define EPS_F   1e-6f
#define DT_F    (1.0f/30.0f)
#define TPB     128

typedef unsigned long long u64;

__device__ __forceinline__ u64 pk2(float x, float y) {
    u64 r; asm("mov.b64 %0,{%1,%2};" : "=l"(r) : "f"(x), "f"(y)); return r;
}
__device__ __forceinline__ void upk2(u64 v, float& x, float& y) {
    asm("mov.b64 {%0,%1},%2;" : "=f"(x), "=f"(y) : "l"(v));
}
__device__ __forceinline__ u64 ffma2(u64 a, u64 b, u64 c) {
    u64 d; asm("fma.rn.f32x2 %0,%1,%2,%3;" : "=l"(d) : "l"(a), "l"(b), "l"(c)); return d;
}

// tanh = copysign(1 - 2e/(1+e), x), e = exp(-2|x|);  |err| ~1e-6.
__device__ __forceinline__ float tanh_fast(float x) {
    float ax = fabsf(x);
    float e;
    asm("ex2.approx.f32 %0, %1;" : "=f"(e) : "f"(ax * -2.885390082f));
    float rc;
    asm("rcp.approx.f32 %0, %1;" : "=f"(rc) : "f"(1.0f + e));
    float r = fmaf(-2.0f * e, rc, 1.0f);
    return copysignf(r, x);
}

// shared layout (floats), weights then h buffer
#define OFF_W1  0        // 11*64 = 704
#define OFF_B1  704      // 64
#define OFF_W2  768      // 64*64 = 4096
#define OFF_B2  4864     // 64
#define OFF_W3  4928     // 64*2 = 128
#define OFF_B3  5056     // 2
#define OFF_H   5060     // 128 elements * 68 floats (stride 272B, padded)
#define H_STRIDE 68
#define SM_FLOATS (OFF_H + 128 * H_STRIDE)      // 5060 + 8704 = 13764
#define SM_BYTES  (SM_FLOATS * 4)               // 55056

__global__ void __launch_bounds__(TPB, 3)
phys_kernel(const float* __restrict__ inp,
            const float* __restrict__ W1, const float* __restrict__ b1,
            const float* __restrict__ W2, const float* __restrict__ b2,
            const float* __restrict__ W3, const float* __restrict__ b3,
            const float* __restrict__ grav, const float* __restrict__ fricp,
            float* __restrict__ out, int nB)
{
    extern __shared__ __align__(16) float sm[];
    int tid = threadIdx.x;

    for (int i = tid; i < 704;  i += TPB) sm[OFF_W1 + i] = W1[i];
    for (int i = tid; i < 64;   i += TPB) sm[OFF_B1 + i] = b1[i];
    for (int i = tid; i < 4096; i += TPB) sm[OFF_W2 + i] = W2[i];
    for (int i = tid; i < 64;   i += TPB) sm[OFF_B2 + i] = b2[i];
    for (int i = tid; i < 128;  i += TPB) sm[OFF_W3 + i] = W3[i];
    if (tid == 0) { sm[OFF_B3] = b3[0]; sm[OFF_B3 + 1] = b3[1]; }
    __syncthreads();

    const int l      = tid & 3;            // lane within slot: owns hidden [16l,16l+16)
    const int wlane  = tid & 31;
    const int slotLB = wlane & ~3;         // warp-lane of slot's lane 0
    const int leBase = tid & ~3;           // CTA-local element base of this slot

    int myE = (blockIdx.x * 32 + (tid >> 2)) * 4 + l;   // own element
    if (myE >= nB) myE = nB - 1;                        // dup-safe (identical writes)

    // own element state
    float p1x, p1y, p2x, p2y, v1x, v1y, v2x, v2y;
    {
        const float* s0 = inp + (size_t)myE * STEPS * 8;
        float4 a = *(const float4*)(s0);
        float4 b = *(const float4*)(s0 + 4);
        p1x = a.x; p1y = a.y; p2x = a.z; p2y = a.w;
        v1x = b.x; v1y = b.y; v2x = b.z; v2y = b.w;
    }

    float g    = grav[0] * 40.0f;
    float fric = fabsf(fricp[0]);

    float* ob = out + (size_t)myE * STEPS * 8;

    const ulonglong2* W1q = (const ulonglong2*)(sm + OFF_W1);  // [11][16] quads
    const u64*        pB1 = (const u64*)(sm + OFF_B1);
    const ulonglong2* W2q = (const ulonglong2*)(sm + OFF_W2);  // [64][16] quads
    const u64*        pB2 = (const u64*)(sm + OFF_B2);
    const u64*        pW3 = (const u64*)(sm + OFF_W3);
    float*            hb  = sm + OFF_H;

    const unsigned FULL = 0xffffffffu;

#pragma unroll 1
    for (int t = 0; t < STEPS; t++) {
        // emit pre-update state for own element
        *(float4*)(ob + t * 8)     = make_float4(p1x, p1y, p2x, p2y);
        *(float4*)(ob + t * 8 + 4) = make_float4(v1x, v1y, v2x, v2y);

        // ---- features for own element ----
        float f[NFEAT];
        {
            float r1  = sqrtf(p1x * p1x + p1y * p1y);
            float th1 = atan2f(p1y, p1x);
            float vr1 = __fdividef(p1x * v1x + p1y * v1y, r1 + EPS_F);
            float vt1 = __fdividef(p1x * v1y - p1y * v1x, r1 * r1 + EPS_F);
            float L1  = r1 * vt1;

            float r2  = sqrtf(p2x * p2x + p2y * p2y);
            float th2 = atan2f(p2y, p2x);
            float vr2 = __fdividef(p2x * v2x + p2y * v2y, r2 + EPS_F);
            float vt2 = __fdividef(p2x * v2y - p2y * v2x, r2 * r2 + EPS_F);
            float L2  = r2 * vt2;

            float dx = p2x - p1x, dy = p2y - p1y;
            float r12 = sqrtf(dx * dx + dy * dy);

            f[0] = r1;  f[1] = th1; f[2] = vr1; f[3] = vt1; f[4] = L1;
            f[5] = r2;  f[6] = th2; f[7] = vr2; f[8] = vt2; f[9] = L2;
            f[10] = r12;
        }

        // ---- layer 1: own 16 hidden outputs for all 4 slot elements ----
        {
            u64 a1[4][8];
#pragma unroll
            for (int e = 0; e < 4; e++)
#pragma unroll
                for (int j = 0; j < 8; j++) a1[e][j] = pB1[8 * l + j];

#pragma unroll
            for (int i = 0; i < NFEAT; i++) {
                u64 fe[4];
#pragma unroll
                for (int e = 0; e < 4; e++) {
                    float v = __shfl_sync(FULL, f[i], slotLB + e);
                    fe[e] = pk2(v, v);
                }
                const ulonglong2* row = W1q + i * 16 + 4 * l;
#pragma unroll
                for (int p = 0; p < 4; p++) {
                    ulonglong2 w = row[p];
#pragma unroll
                    for (int e = 0; e < 4; e++) {
                        a1[e][2 * p]     = ffma2(fe[e], w.x, a1[e][2 * p]);
                        a1[e][2 * p + 1] = ffma2(fe[e], w.y, a1[e][2 * p + 1]);
                    }
                }
            }

            // tanh -> h buffer (rotated quad order spreads write banks)
#pragma unroll
            for (int e = 0; e < 4; e++) {
                float hh[16];
#pragma unroll
                for (int j = 0; j < 8; j++) {
                    float x0, x1; upk2(a1[e][j], x0, x1);
                    hh[2 * j]     = tanh_fast(x0);
                    hh[2 * j + 1] = tanh_fast(x1);
                }
                float* dst = hb + (leBase + e) * H_STRIDE + 16 * l;
#pragma unroll
                for (int qi = 0; qi < 4; qi++) {
                    int q = (qi + l) & 3;
                    *(float4*)(dst + 4 * q) =
                        make_float4(hh[4 * q], hh[4 * q + 1], hh[4 * q + 2], hh[4 * q + 3]);
                }
            }
        }
        __syncwarp();

        // ---- layer 2: own 16 outputs over all 64 hidden, all 4 elements ----
        u64 a2[4][8];
#pragma unroll
        for (int e = 0; e < 4; e++)
#pragma unroll
            for (int j = 0; j < 8; j++) a2[e][j] = pB2[8 * l + j];

#pragma unroll 4
        for (int m = 0; m < 16; m++) {
            float hv[4][4];
#pragma unroll
            for (int e = 0; e < 4; e++) {
                float4 q = *(const float4*)(hb + (leBase + e) * H_STRIDE + 4 * m);
                hv[e][0] = q.x; hv[e][1] = q.y; hv[e][2] = q.z; hv[e][3] = q.w;
            }
#pragma unroll
            for (int kk = 0; kk < 4; kk++) {
                int k = 4 * m + kk;
                const ulonglong2* row = W2q + k * 16 + 4 * l;
                u64 hk[4];
#pragma unroll
                for (int e = 0; e < 4; e++) hk[e] = pk2(hv[e][kk], hv[e][kk]);
#pragma unroll
                for (int p = 0; p < 4; p++) {
                    ulonglong2 w = row[p];
#pragma unroll
                    for (int e = 0; e < 4; e++) {
                        a2[e][2 * p]     = ffma2(hk[e], w.x, a2[e][2 * p]);
                        a2[e][2 * p + 1] = ffma2(hk[e], w.y, a2[e][2 * p + 1]);
                    }
                }
            }
        }
        __syncwarp();

        // ---- layer 3: partial dot over own 16 hidden, per element ----
        u64 c[4], d[4];
        {
            u64 binit = (l == 0) ? pk2(sm[OFF_B3], sm[OFF_B3 + 1]) : pk2(0.0f, 0.0f);
#pragma unroll
            for (int e = 0; e < 4; e++) { c[e] = binit; d[e] = pk2(0.0f, 0.0f); }
#pragma unroll
            for (int j = 0; j < 8; j++) {
                int kg = 16 * l + 2 * j;
                u64 w0 = pW3[kg];
                u64 w1 = pW3[kg + 1];
#pragma unroll
                for (int e = 0; e < 4; e++) {
                    float x0, x1; upk2(a2[e][j], x0, x1);
                    float g0 = tanh_fast(x0), g1 = tanh_fast(x1);
                    c[e] = ffma2(pk2(g0, g0), w0, c[e]);
                    d[e] = ffma2(pk2(g1, g1), w1, d[e]);
                }
            }
        }

        // butterfly-reduce each element's partial across the 4 slot lanes
        float cxe[4], cye[4];
#pragma unroll
        for (int e = 0; e < 4; e++) {
            float x0, y0, x1, y1;
            upk2(c[e], x0, y0); upk2(d[e], x1, y1);
            float sx = x0 + x1, sy = y0 + y1;
            float u;
            u = __shfl_xor_sync(FULL, sx, 1); sx = sx + u;   // commutative: bitwise-identical
            u = __shfl_xor_sync(FULL, sx, 2); sx = sx + u;
            u = __shfl_xor_sync(FULL, sy, 1); sy = sy + u;
            u = __shfl_xor_sync(FULL, sy, 2); sy = sy + u;
            cxe[e] = sx * 0.1f;
            cye[e] = sy * 0.1f;
        }
        float corrx = (l == 0) ? cxe[0] : (l == 1) ? cxe[1] : (l == 2) ? cxe[2] : cxe[3];
        float corry = (l == 0) ? cye[0] : (l == 1) ? cye[1] : (l == 2) ? cye[2] : cye[3];

        // ---- integrate own element ----
        float a1x = corrx - fric * v1x;
        float a1y = g + corry - fric * v1y;
        float a2x = corrx - fric * v2x;
        float a2y = g + corry - fric * v2y;

        v1x += a1x * DT_F;  v1y += a1y * DT_F;
        v2x += a2x * DT_F;  v2y += a2y * DT_F;
        p1x += v1x * DT_F;  p1y += v1y * DT_F;
        p2x += v2x * DT_F;  p2y += v2y * DT_F;

        bool m;
        m = (p1x < 20.0f) || (p1x > 780.0f); v1x = m ? -0.8f * v1x : v1x;
        p1x = fminf(fmaxf(p1x, 20.0f), 780.0f);
        m = (p1y < 20.0f) || (p1y > 580.0f); v1y = m ? -0.8f * v1y : v1y;
        p1y = fminf(fmaxf(p1y, 20.0f), 580.0f);

        m = (p2x < 20.0f) || (p2x > 780.0f); v2x = m ? -0.8f * v2x : v2x;
        p2x = fminf(fmaxf(p2x, 20.0f), 780.0f);
        m = (p2y < 20.0f) || (p2y > 580.0f); v2y = m ? -0.8f * v2y : v2y;
        p2y = fminf(fmaxf(p2y, 20.0f), 580.0f);
    }
}

extern "C" void kernel_launch(void* const* d_in, const int* in_sizes, int n_in,
                              void* d_out, int out_size) {
    const float* inp  = (const float*)d_in[0];
    const float* W1   = (const float*)d_in[1];
    const float* b1   = (const float*)d_in[2];
    const float* W2   = (const float*)d_in[3];
    const float* b2   = (const float*)d_in[4];
    const float* W3   = (const float*)d_in[5];
    const float* b3   = (const float*)d_in[6];
    const float* grav = (const float*)d_in[7];
    const float* fric = (const float*)d_in[8];
    float* out = (float*)d_out;

    int nB = in_sizes[0] / (STEPS * 8);

    static int smem_set = 0;
    if (!smem_set) {
        cudaFuncSetAttribute(phys_kernel,
                             cudaFuncAttributeMaxDynamicSharedMemorySize, SM_BYTES);
        smem_set = 1;
    }

    int nElems = ((nB + 127) / 128) * 128;      // 128 elements per CTA
    int grid   = nElems / 128;
    phys_kernel<<<grid, TPB, SM_BYTES>>>(inp, W1, b1, W2, b2, W3, b3,
                                         grav, fric, out, nB);
}

// round 7
// speedup vs baseline: 4.9882x; 1.6590x over previous
#include <cuda_runtime.h>

// MinimalPhysicsModel: 50-step recurrent sim + MLP(11->64->64->2, tanh).
// S=4 lanes/slot, E=4 elements/slot. R7: interleaved quad ownership
// (lane l owns row-quads {l,l+4,l+8,l+12}) makes every weight LDS.128
// request 64B-contiguous (1 wavefront), and transposed h staging
// h2[unit][elem] makes every layer-2 h load a 128B-contiguous broadcast
// (1 wavefront). Packed fma.rn.f32x2 throughout.

#define STEPS   50
#define HID     64
#define NFEAT   11
#define EPS_F   1e-6f
#define DT_F    (1.0f/30.0f)
#define TPB     128

typedef unsigned long long u64;

__device__ __forceinline__ u64 pk2(float x, float y) {
    u64 r; asm("mov.b64 %0,{%1,%2};" : "=l"(r) : "f"(x), "f"(y)); return r;
}
__device__ __forceinline__ void upk2(u64 v, float& x, float& y) {
    asm("mov.b64 {%0,%1},%2;" : "=f"(x), "=f"(y) : "l"(v));
}
__device__ __forceinline__ u64 ffma2(u64 a, u64 b, u64 c) {
    u64 d; asm("fma.rn.f32x2 %0,%1,%2,%3;" : "=l"(d) : "l"(a), "l"(b), "l"(c)); return d;
}

// tanh = copysign(1 - 2e/(1+e), x), e = exp(-2|x|);  |err| ~1e-6.
__device__ __forceinline__ float tanh_fast(float x) {
    float ax = fabsf(x);
    float e;
    asm("ex2.approx.f32 %0, %1;" : "=f"(e) : "f"(ax * -2.885390082f));
    float rc;
    asm("rcp.approx.f32 %0, %1;" : "=f"(rc) : "f"(1.0f + e));
    float r = fmaf(-2.0f * e, rc, 1.0f);
    return copysignf(r, x);
}

// shared layout (floats)
#define OFF_W1  0        // 11*64 = 704
#define OFF_B1  704      // 64
#define OFF_W2  768      // 64*64 = 4096
#define OFF_B2  4864     // 64
#define OFF_W3  4928     // 64*2 = 128
#define OFF_B3  5056     // 2
#define OFF_H   5060     // h2[64][132]: unit-major, elem stride 1, row pad 4
#define H_R     132
#define SM_FLOATS (OFF_H + HID * H_R)           // 5060 + 8448 = 13508
#define SM_BYTES  (SM_FLOATS * 4)               // 54032

__global__ void __launch_bounds__(TPB, 3)
phys_kernel(const float* __restrict__ inp,
            const float* __restrict__ W1, const float* __restrict__ b1,
            const float* __restrict__ W2, const float* __restrict__ b2,
            const float* __restrict__ W3, const float* __restrict__ b3,
            const float* __restrict__ grav, const float* __restrict__ fricp,
            float* __restrict__ out, int nB)
{
    extern __shared__ __align__(16) float sm[];
    int tid = threadIdx.x;

    for (int i = tid; i < 704;  i += TPB) sm[OFF_W1 + i] = W1[i];
    for (int i = tid; i < 64;   i += TPB) sm[OFF_B1 + i] = b1[i];
    for (int i = tid; i < 4096; i += TPB) sm[OFF_W2 + i] = W2[i];
    for (int i = tid; i < 64;   i += TPB) sm[OFF_B2 + i] = b2[i];
    for (int i = tid; i < 128;  i += TPB) sm[OFF_W3 + i] = W3[i];
    if (tid == 0) { sm[OFF_B3] = b3[0]; sm[OFF_B3 + 1] = b3[1]; }
    __syncthreads();

    const int l      = tid & 3;            // owns row-quads {l, l+4, l+8, l+12}
    const int wlane  = tid & 31;
    const int slotLB = wlane & ~3;         // warp-lane of slot's lane 0
    const int leBase = tid & ~3;           // CTA-local element base of this slot

    int myE = (blockIdx.x * 32 + (tid >> 2)) * 4 + l;
    if (myE >= nB) myE = nB - 1;           // dup-safe (identical writes)

    float p1x, p1y, p2x, p2y, v1x, v1y, v2x, v2y;
    {
        const float* s0 = inp + (size_t)myE * STEPS * 8;
        float4 a = *(const float4*)(s0);
        float4 b = *(const float4*)(s0 + 4);
        p1x = a.x; p1y = a.y; p2x = a.z; p2y = a.w;
        v1x = b.x; v1y = b.y; v2x = b.z; v2y = b.w;
    }

    float g    = grav[0] * 40.0f;
    float fric = fabsf(fricp[0]);

    float* ob = out + (size_t)myE * STEPS * 8;

    const ulonglong2* W1q  = (const ulonglong2*)(sm + OFF_W1);  // [11][16]
    const ulonglong2* B1q  = (const ulonglong2*)(sm + OFF_B1);  // [16]
    const ulonglong2* W2q  = (const ulonglong2*)(sm + OFF_W2);  // [64][16]
    const ulonglong2* B2q  = (const ulonglong2*)(sm + OFF_B2);  // [16]
    const ulonglong2* W3q2 = (const ulonglong2*)(sm + OFF_W3);  // [32]
    float*            hb   = sm + OFF_H;

    const unsigned FULL = 0xffffffffu;

#pragma unroll 1
    for (int t = 0; t < STEPS; t++) {
        *(float4*)(ob + t * 8)     = make_float4(p1x, p1y, p2x, p2y);
        *(float4*)(ob + t * 8 + 4) = make_float4(v1x, v1y, v2x, v2y);

        // ---- features for own element ----
        float f[NFEAT];
        {
            float r1  = sqrtf(p1x * p1x + p1y * p1y);
            float th1 = atan2f(p1y, p1x);
            float vr1 = __fdividef(p1x * v1x + p1y * v1y, r1 + EPS_F);
            float vt1 = __fdividef(p1x * v1y - p1y * v1x, r1 * r1 + EPS_F);
            float L1  = r1 * vt1;

            float r2  = sqrtf(p2x * p2x + p2y * p2y);
            float th2 = atan2f(p2y, p2x);
            float vr2 = __fdividef(p2x * v2x + p2y * v2y, r2 + EPS_F);
            float vt2 = __fdividef(p2x * v2y - p2y * v2x, r2 * r2 + EPS_F);
            float L2  = r2 * vt2;

            float dx = p2x - p1x, dy = p2y - p1y;
            float r12 = sqrtf(dx * dx + dy * dy);

            f[0] = r1;  f[1] = th1; f[2] = vr1; f[3] = vt1; f[4] = L1;
            f[5] = r2;  f[6] = th2; f[7] = vr2; f[8] = vt2; f[9] = L2;
            f[10] = r12;
        }

        // ---- layer 1: own 16 hidden units (interleaved quads) x 4 elems ----
        {
            u64 a1[4][8];
#pragma unroll
            for (int gq = 0; gq < 4; gq++) {
                ulonglong2 bq = B1q[4 * gq + l];
#pragma unroll
                for (int e = 0; e < 4; e++) {
                    a1[e][2 * gq]     = bq.x;
                    a1[e][2 * gq + 1] = bq.y;
                }
            }

#pragma unroll
            for (int i = 0; i < NFEAT; i++) {
                u64 fe[4];
#pragma unroll
                for (int e = 0; e < 4; e++) {
                    float v = __shfl_sync(FULL, f[i], slotLB + e);
                    fe[e] = pk2(v, v);
                }
#pragma unroll
                for (int gq = 0; gq < 4; gq++) {
                    ulonglong2 w = W1q[i * 16 + 4 * gq + l];   // 64B-contig request
#pragma unroll
                    for (int e = 0; e < 4; e++) {
                        a1[e][2 * gq]     = ffma2(fe[e], w.x, a1[e][2 * gq]);
                        a1[e][2 * gq + 1] = ffma2(fe[e], w.y, a1[e][2 * gq + 1]);
                    }
                }
            }

            // tanh + transposed store: h2[u][elem], u = 16*gq + 4*l + j
#pragma unroll
            for (int gq = 0; gq < 4; gq++) {
                float tq[4][4];
#pragma unroll
                for (int e = 0; e < 4; e++) {
                    float x0, x1, x2, x3;
                    upk2(a1[e][2 * gq],     x0, x1);
                    upk2(a1[e][2 * gq + 1], x2, x3);
                    tq[e][0] = tanh_fast(x0);
                    tq[e][1] = tanh_fast(x1);
                    tq[e][2] = tanh_fast(x2);
                    tq[e][3] = tanh_fast(x3);
                }
#pragma unroll
                for (int j = 0; j < 4; j++) {
                    int u = 16 * gq + 4 * l + j;
                    *(float4*)(hb + u * H_R + leBase) =
                        make_float4(tq[0][j], tq[1][j], tq[2][j], tq[3][j]);
                }
            }
        }
        __syncwarp();

        // ---- layer 2: own 16 units over all 64 hidden, 4 elems ----
        u64 a2[4][8];
#pragma unroll
        for (int gq = 0; gq < 4; gq++) {
            ulonglong2 bq = B2q[4 * gq + l];
#pragma unroll
            for (int e = 0; e < 4; e++) {
                a2[e][2 * gq]     = bq.x;
                a2[e][2 * gq + 1] = bq.y;
            }
        }

#pragma unroll 8
        for (int k = 0; k < HID; k++) {
            float4 hv = *(const float4*)(hb + k * H_R + leBase);  // 128B bcast, 1 wf
            u64 hk[4];
            hk[0] = pk2(hv.x, hv.x);
            hk[1] = pk2(hv.y, hv.y);
            hk[2] = pk2(hv.z, hv.z);
            hk[3] = pk2(hv.w, hv.w);
#pragma unroll
            for (int gq = 0; gq < 4; gq++) {
                ulonglong2 w = W2q[k * 16 + 4 * gq + l];          // 64B-contig request
#pragma unroll
                for (int e = 0; e < 4; e++) {
                    a2[e][2 * gq]     = ffma2(hk[e], w.x, a2[e][2 * gq]);
                    a2[e][2 * gq + 1] = ffma2(hk[e], w.y, a2[e][2 * gq + 1]);
                }
            }
        }
        __syncwarp();

        // ---- layer 3: partial dot over own 16 units, per element ----
        u64 c[4], d[4];
        {
            u64 binit = (l == 0) ? pk2(sm[OFF_B3], sm[OFF_B3 + 1]) : pk2(0.0f, 0.0f);
#pragma unroll
            for (int e = 0; e < 4; e++) { c[e] = binit; d[e] = pk2(0.0f, 0.0f); }
#pragma unroll
            for (int gq = 0; gq < 4; gq++) {
                // units 16gq+4l+{0..3} -> W3 pair u64 idx 16gq+4l.. = ull2 idx 8gq+2l, +1
                ulonglong2 wA = W3q2[8 * gq + 2 * l];
                ulonglong2 wB = W3q2[8 * gq + 2 * l + 1];
#pragma unroll
                for (int e = 0; e < 4; e++) {
                    float x0, x1, x2, x3;
                    upk2(a2[e][2 * gq],     x0, x1);
                    upk2(a2[e][2 * gq + 1], x2, x3);
                    float g0 = tanh_fast(x0), g1 = tanh_fast(x1);
                    float g2 = tanh_fast(x2), g3 = tanh_fast(x3);
                    c[e] = ffma2(pk2(g0, g0), wA.x, c[e]);
                    d[e] = ffma2(pk2(g1, g1), wA.y, d[e]);
                    c[e] = ffma2(pk2(g2, g2), wB.x, c[e]);
                    d[e] = ffma2(pk2(g3, g3), wB.y, d[e]);
                }
            }
        }

        // butterfly-reduce each element's partial across the 4 slot lanes
        float corrx, corry;
#pragma unroll
        for (int e = 0; e < 4; e++) {
            float x0, y0, x1, y1;
            upk2(c[e], x0, y0); upk2(d[e], x1, y1);
            float sx = x0 + x1, sy = y0 + y1;
            float u;
            u = __shfl_xor_sync(FULL, sx, 1); sx = sx + u;   // commutative: identical on all lanes
            u = __shfl_xor_sync(FULL, sx, 2); sx = sx + u;
            u = __shfl_xor_sync(FULL, sy, 1); sy = sy + u;
            u = __shfl_xor_sync(FULL, sy, 2); sy = sy + u;
            if (e == l) { corrx = sx * 0.1f; corry = sy * 0.1f; }
        }

        // ---- integrate own element ----
        float a1x = corrx - fric * v1x;
        float a1y = g + corry - fric * v1y;
        float a2x = corrx - fric * v2x;
        float a2y = g + corry - fric * v2y;

        v1x += a1x * DT_F;  v1y += a1y * DT_F;
        v2x += a2x * DT_F;  v2y += a2y * DT_F;
        p1x += v1x * DT_F;  p1y += v1y * DT_F;
        p2x += v2x * DT_F;  p2y += v2y * DT_F;

        bool m;
        m = (p1x < 20.0f) || (p1x > 780.0f); v1x = m ? -0.8f * v1x : v1x;
        p1x = fminf(fmaxf(p1x, 20.0f), 780.0f);
        m = (p1y < 20.0f) || (p1y > 580.0f); v1y = m ? -0.8f * v1y : v1y;
        p1y = fminf(fmaxf(p1y, 20.0f), 580.0f);

        m = (p2x < 20.0f) || (p2x > 780.0f); v2x = m ? -0.8f * v2x : v2x;
        p2x = fminf(fmaxf(p2x, 20.0f), 780.0f);
        m = (p2y < 20.0f) || (p2y > 580.0f); v2y = m ? -0.8f * v2y : v2y;
        p2y = fminf(fmaxf(p2y, 20.0f), 580.0f);
    }
}

extern "C" void kernel_launch(void* const* d_in, const int* in_sizes, int n_in,
                              void* d_out, int out_size) {
    const float* inp  = (const float*)d_in[0];
    const float* W1   = (const float*)d_in[1];
    const float* b1   = (const float*)d_in[2];
    const float* W2   = (const float*)d_in[3];
    const float* b2   = (const float*)d_in[4];
    const float* W3   = (const float*)d_in[5];
    const float* b3   = (const float*)d_in[6];
    const float* grav = (const float*)d_in[7];
    const float* fric = (const float*)d_in[8];
    float* out = (float*)d_out;

    int nB = in_sizes[0] / (STEPS * 8);

    static int smem_set = 0;
    if (!smem_set) {
        cudaFuncSetAttribute(phys_kernel,
                             cudaFuncAttributeMaxDynamicSharedMemorySize, SM_BYTES);
        smem_set = 1;
    }

    int nElems = ((nB + 127) / 128) * 128;      // 128 elements per CTA
    int grid   = nElems / 128;
    phys_kernel<<<grid, TPB, SM_BYTES>>>(inp, W1, b1, W2, b2, W3, b3,
                                         grav, fric, out, nB);
}